// round 1
// baseline (speedup 1.0000x reference)
#include <cuda_runtime.h>
#include <cstdint>

#define B_ 8192
#define C_ 64
#define K_ 256
#define D_ 64

// ---------------- scratch (static __device__ — no allocations) ----------------
__device__ unsigned long long g_maxpack[B_ * C_];  // key<<32 | (255-k)
__device__ unsigned long long g_minpack[B_ * C_];
__device__ float g_sum[C_];
__device__ float g_sumsq[C_];

// monotone float -> uint key (total order matching float <)
__device__ __forceinline__ unsigned fkey(float f) {
    unsigned u = __float_as_uint(f);
    return (u & 0x80000000u) ? ~u : (u | 0x80000000u);
}
__device__ __forceinline__ float fkey_inv(unsigned key) {
    unsigned u = (key & 0x80000000u) ? (key ^ 0x80000000u) : ~key;
    return __uint_as_float(u);
}

__global__ void init_kernel() {
    int t = threadIdx.x;
    if (t < C_) { g_sum[t] = 0.f; g_sumsq[t] = 0.f; }
}

// ---------------- main scoring kernel ----------------
// grid = (C_, B_/64); block = 256; each thread owns an 8x8 micro-tile.
// smem: sW [D_][K_] (d-major, 64KB), sA [D_][64] (d-major, 16KB)
__global__ void __launch_bounds__(256, 2)
score_kernel(const float* __restrict__ inp, const float* __restrict__ cent) {
    extern __shared__ float sm[];
    float* sW = sm;              // 64 x 256
    float* sA = sm + D_ * K_;    // 64 x 64

    const int c  = blockIdx.x;
    const int b0 = blockIdx.y * 64;

    // --- load centroids[c] transposed to d-major ---
    const float4* wg = (const float4*)(cent + (size_t)c * K_ * D_);
    for (int t = threadIdx.x; t < (K_ * D_) / 4; t += 256) {
        int k = t >> 4;
        int d = (t & 15) << 2;
        float4 v = wg[t];
        sW[(d + 0) * K_ + k] = v.x;
        sW[(d + 1) * K_ + k] = v.y;
        sW[(d + 2) * K_ + k] = v.z;
        sW[(d + 3) * K_ + k] = v.w;
    }
    // --- load input tile transposed to d-major ---
    const float4* ag = (const float4*)inp;  // inputs[b][c][d]
    for (int t = threadIdx.x; t < 64 * 16; t += 256) {
        int r = t >> 4;
        int d4 = t & 15;
        float4 v = ag[(size_t)(b0 + r) * (C_ * D_ / 4) + c * (D_ / 4) + d4];
        int d = d4 << 2;
        sA[(d + 0) * 64 + r] = v.x;
        sA[(d + 1) * 64 + r] = v.y;
        sA[(d + 2) * 64 + r] = v.z;
        sA[(d + 3) * 64 + r] = v.w;
    }
    __syncthreads();

    const int tx = threadIdx.x & 31;   // col group: cols tx*8 .. tx*8+7
    const int ty = threadIdx.x >> 5;   // row group: rows ty*8 .. ty*8+7

    float acc[8][8];
#pragma unroll
    for (int i = 0; i < 8; i++)
#pragma unroll
        for (int j = 0; j < 8; j++) acc[i][j] = 0.f;

    const float* ab = sA + ty * 8;
    const float* wb = sW + tx * 8;

#pragma unroll 4
    for (int d = 0; d < D_; d++) {
        float a[8], w[8];
        *(float4*)&a[0] = *(const float4*)(ab + d * 64);
        *(float4*)&a[4] = *(const float4*)(ab + d * 64 + 4);
        *(float4*)&w[0] = *(const float4*)(wb + d * K_);
        *(float4*)&w[4] = *(const float4*)(wb + d * K_ + 4);
#pragma unroll
        for (int i = 0; i < 8; i++)
#pragma unroll
            for (int j = 0; j < 8; j++)
                acc[i][j] = fmaf(a[i], w[j], acc[i][j]);
    }

    // --- per-row max/argmax + min/argmin (first-occurrence tie-break) ---
#pragma unroll
    for (int i = 0; i < 8; i++) {
        unsigned long long mx = 0ull, mn = 0ull;
#pragma unroll
        for (int j = 0; j < 8; j++) {
            unsigned kk = fkey(acc[i][j]);
            unsigned idxp = (unsigned)(255 - (tx * 8 + j));
            unsigned long long pmx = ((unsigned long long)kk << 32) | idxp;
            unsigned long long pmn = ((unsigned long long)(~kk) << 32) | idxp;
            mx = (pmx > mx) ? pmx : mx;
            mn = (pmn > mn) ? pmn : mn;
        }
#pragma unroll
        for (int s = 16; s > 0; s >>= 1) {
            unsigned long long o = __shfl_xor_sync(0xffffffffu, mx, s);
            mx = (o > mx) ? o : mx;
            o = __shfl_xor_sync(0xffffffffu, mn, s);
            mn = (o > mn) ? o : mn;
        }
        if (tx == 0) {
            int b = b0 + ty * 8 + i;
            g_maxpack[(size_t)b * C_ + c] = mx;
            g_minpack[(size_t)b * C_ + c] = mn;
        }
    }

    // --- channel sum / sumsq ---
    float s = 0.f, s2 = 0.f;
#pragma unroll
    for (int i = 0; i < 8; i++)
#pragma unroll
        for (int j = 0; j < 8; j++) {
            float v = acc[i][j];
            s += v;
            s2 = fmaf(v, v, s2);
        }
#pragma unroll
    for (int sh = 16; sh > 0; sh >>= 1) {
        s  += __shfl_xor_sync(0xffffffffu, s,  sh);
        s2 += __shfl_xor_sync(0xffffffffu, s2, sh);
    }
    __syncthreads();  // done reading sA; reuse it for cross-warp reduce
    if (tx == 0) { sA[ty] = s; sA[8 + ty] = s2; }
    __syncthreads();
    if (threadIdx.x == 0) {
        float t1 = 0.f, t2 = 0.f;
#pragma unroll
        for (int w = 0; w < 8; w++) { t1 += sA[w]; t2 += sA[8 + w]; }
        atomicAdd(&g_sum[c], t1);
        atomicAdd(&g_sumsq[c], t2);
    }
}

// ---------------- finalize: BN affine + select ----------------
__global__ void finalize_kernel(const float* __restrict__ gamma,
                                const float* __restrict__ beta,
                                float* __restrict__ out_codes,
                                float* __restrict__ out_mse) {
    int tid = blockIdx.x * 256 + threadIdx.x;
    if (tid >= B_ * C_) return;
    int c = tid & (C_ - 1);
    const float Ninv = 1.f / ((float)B_ * (float)K_);
    float mean = g_sum[c] * Ninv;
    float var  = fmaf(-mean, mean, g_sumsq[c] * Ninv);
    float scale = gamma[c] * rsqrtf(var + 1e-5f);
    float shift = fmaf(-mean, scale, beta[c]);

    unsigned long long p;
    float v;
    if (scale >= 0.f) {
        p = g_maxpack[tid];
        v = fkey_inv((unsigned)(p >> 32));
    } else {
        p = g_minpack[tid];
        v = fkey_inv(~(unsigned)(p >> 32));
    }
    int k = 255 - (int)(p & 0xFFFFFFFFull);
    out_codes[tid] = (float)k;
    out_mse[tid]   = fmaf(v, scale, shift);
}

// ---------------- centroids passthrough ----------------
__global__ void copy_kernel(const float4* __restrict__ src,
                            float4* __restrict__ dst, int n4) {
    int i = blockIdx.x * blockDim.x + threadIdx.x;
    if (i < n4) dst[i] = src[i];
}

extern "C" void kernel_launch(void* const* d_in, const int* in_sizes, int n_in,
                              void* d_out, int out_size) {
    const float* inp   = (const float*)d_in[0];
    const float* cent  = (const float*)d_in[1];
    const float* gamma = (const float*)d_in[2];
    const float* beta  = (const float*)d_in[3];
    float* out = (float*)d_out;

    const int smem = (D_ * K_ + D_ * 64) * (int)sizeof(float);  // 81920 B
    cudaFuncSetAttribute(score_kernel,
                         cudaFuncAttributeMaxDynamicSharedMemorySize, smem);

    init_kernel<<<1, 64>>>();

    dim3 grid(C_, B_ / 64);
    score_kernel<<<grid, 256, smem>>>(inp, cent);

    finalize_kernel<<<(B_ * C_ + 255) / 256, 256>>>(gamma, beta,
                                                    out, out + B_ * C_);

    if (out_size >= 2 * B_ * C_ + C_ * K_ * D_) {
        int n4 = (C_ * K_ * D_) / 4;
        copy_kernel<<<(n4 + 255) / 256, 256>>>((const float4*)cent,
                                               (float4*)(out + 2 * B_ * C_), n4);
    }
}

// round 4
// speedup vs baseline: 1.4855x; 1.4855x over previous
#include <cuda_runtime.h>
#include <cuda_bf16.h>
#include <cstdint>

#define B_ 8192
#define C_ 64
#define K_ 256
#define D_ 64
#define BTILE 128

// ---------------- scratch (static __device__) ----------------
__device__ float g_val[B_ * C_];
__device__ int   g_idx[B_ * C_];
__device__ float g_sum[C_];
__device__ float g_sumsq[C_];

// monotone float -> uint key (total order matching float <)
__device__ __forceinline__ unsigned fkey(float f) {
    unsigned u = __float_as_uint(f);
    return (u & 0x80000000u) ? ~u : (u | 0x80000000u);
}
__device__ __forceinline__ float fkey_inv(unsigned key) {
    unsigned u = (key & 0x80000000u) ? (key ^ 0x80000000u) : ~key;
    return __uint_as_float(u);
}

__device__ __forceinline__ uint32_t smem_u32(const void* p) {
    uint32_t a;
    asm("{ .reg .u64 t; cvta.to.shared.u64 t, %1; cvt.u32.u64 %0, t; }" : "=r"(a) : "l"(p));
    return a;
}

#define LDSM_X4(r0, r1, r2, r3, addr) \
    asm volatile("ldmatrix.sync.aligned.m8n8.x4.shared.b16 {%0,%1,%2,%3}, [%4];" \
        : "=r"(r0), "=r"(r1), "=r"(r2), "=r"(r3) : "r"(addr))
#define MMA_BF16(c, a, b0, b1) \
    asm volatile("mma.sync.aligned.m16n8k16.row.col.f32.bf16.bf16.f32 " \
        "{%0,%1,%2,%3}, {%4,%5,%6,%7}, {%8,%9}, {%0,%1,%2,%3};" \
        : "+f"((c)[0]), "+f"((c)[1]), "+f"((c)[2]), "+f"((c)[3]) \
        : "r"((a)[0]), "r"((a)[1]), "r"((a)[2]), "r"((a)[3]), "r"(b0), "r"(b1))

// 3-term bf16 split
__device__ __forceinline__ void split3(float x, uint16_t& h, uint16_t& m, uint16_t& l) {
    __nv_bfloat16 bh = __float2bfloat16_rn(x);
    float r1 = x - __bfloat162float(bh);
    __nv_bfloat16 bm = __float2bfloat16_rn(r1);
    float r2 = r1 - __bfloat162float(bm);
    __nv_bfloat16 bl = __float2bfloat16_rn(r2);
    h = __bfloat16_as_ushort(bh);
    m = __bfloat16_as_ushort(bm);
    l = __bfloat16_as_ushort(bl);
}

// ---------------- smem layout (bytes) ----------------
#define SM_RED   0
#define SM_WSUM  4096
#define SM_A     8192                 // 3 parts x (128 rows x 128B) = 49152
#define SM_B     (8192 + 49152)       // 3 parts x (256 rows x 128B) = 98304
#define SM_TOTAL (8192 + 49152 + 98304)   // 155648

#define A_PART   16384
#define B_PART   32768

__global__ void init_kernel() {
    int t = threadIdx.x;
    if (t < C_) { g_sum[t] = 0.f; g_sumsq[t] = 0.f; }
}

// swizzled byte offset within a part tile: row stride 128B, XOR bits[6:4] by row&7
__device__ __forceinline__ uint32_t sw_off(int row, int cbyte) {
    return (uint32_t)(row * 128 + (cbyte ^ ((row & 7) << 4)));
}

__global__ void __launch_bounds__(512, 1)
score_kernel(const float* __restrict__ inp, const float* __restrict__ cent,
             const float* __restrict__ gamma) {
    extern __shared__ char smem[];
    const int tid  = threadIdx.x;
    const int lane = tid & 31;
    const int wid  = tid >> 5;
    const int warpM = wid & 7;        // rows 16*warpM .. +15
    const int warpN = wid >> 3;       // cols 128*warpN .. +127
    const int c  = blockIdx.x;
    const int b0 = blockIdx.y * BTILE;

    // ---- fill A: 128 x 64 fp32 -> 3 bf16 parts, swizzled ----
    {
        const float* Ab = inp + (size_t)b0 * (C_ * D_) + (size_t)c * D_;
        for (int t = tid; t < BTILE * 16; t += 512) {
            int r = t >> 4;
            int d = (t & 15) << 2;
            float4 v = *(const float4*)(Ab + (size_t)r * (C_ * D_) + d);
            uint16_t h[4], m[4], l[4];
            split3(v.x, h[0], m[0], l[0]);
            split3(v.y, h[1], m[1], l[1]);
            split3(v.z, h[2], m[2], l[2]);
            split3(v.w, h[3], m[3], l[3]);
            uint32_t o = sw_off(r, d * 2);
            *(uint64_t*)(smem + SM_A + o)              = (uint64_t)h[0] | ((uint64_t)h[1] << 16) | ((uint64_t)h[2] << 32) | ((uint64_t)h[3] << 48);
            *(uint64_t*)(smem + SM_A + A_PART + o)     = (uint64_t)m[0] | ((uint64_t)m[1] << 16) | ((uint64_t)m[2] << 32) | ((uint64_t)m[3] << 48);
            *(uint64_t*)(smem + SM_A + 2 * A_PART + o) = (uint64_t)l[0] | ((uint64_t)l[1] << 16) | ((uint64_t)l[2] << 32) | ((uint64_t)l[3] << 48);
        }
    }
    // ---- fill B: 256 x 64 fp32 -> 3 bf16 parts, swizzled ----
    {
        const float* Bb = cent + (size_t)c * (K_ * D_);
        for (int t = tid; t < K_ * 16; t += 512) {
            int r = t >> 4;
            int d = (t & 15) << 2;
            float4 v = *(const float4*)(Bb + (size_t)r * D_ + d);
            uint16_t h[4], m[4], l[4];
            split3(v.x, h[0], m[0], l[0]);
            split3(v.y, h[1], m[1], l[1]);
            split3(v.z, h[2], m[2], l[2]);
            split3(v.w, h[3], m[3], l[3]);
            uint32_t o = sw_off(r, d * 2);
            *(uint64_t*)(smem + SM_B + o)              = (uint64_t)h[0] | ((uint64_t)h[1] << 16) | ((uint64_t)h[2] << 32) | ((uint64_t)h[3] << 48);
            *(uint64_t*)(smem + SM_B + B_PART + o)     = (uint64_t)m[0] | ((uint64_t)m[1] << 16) | ((uint64_t)m[2] << 32) | ((uint64_t)m[3] << 48);
            *(uint64_t*)(smem + SM_B + 2 * B_PART + o) = (uint64_t)l[0] | ((uint64_t)l[1] << 16) | ((uint64_t)l[2] << 32) | ((uint64_t)l[3] << 48);
        }
    }
    __syncthreads();

    const uint32_t smem_base = smem_u32(smem);
    const uint32_t sA = smem_base + SM_A;
    const uint32_t sB = smem_base + SM_B;

    // ldmatrix per-lane addressing (non-trans for BOTH A and B: row.col mma,
    // B stored [n][k] k-contiguous == col-major KxN)
    const int arow = warpM * 16 + (lane & 15);
    const uint32_t aoff0 = (uint32_t)(arow * 128);
    const uint32_t aswz = (uint32_t)((arow & 7) << 4);
    const int brow = warpN * 128 + (lane & 15);
    const uint32_t boff0 = (uint32_t)(brow * 128);
    const uint32_t bswz = (uint32_t)((brow & 7) << 4);
    const uint32_t lane16 = (uint32_t)(lane & 16);

    float acc[16][4];
#pragma unroll
    for (int j = 0; j < 16; j++)
#pragma unroll
        for (int e = 0; e < 4; e++) acc[j][e] = 0.f;

#pragma unroll
    for (int ks = 0; ks < 4; ks++) {
        const uint32_t kcb = (uint32_t)(ks * 32) + lane16;   // byte col for this k-step

        // load 3 A fragments (hi, mid, lo)
        uint32_t aH[4], aM[4], aL[4];
        {
            uint32_t addr = sA + aoff0 + (kcb ^ aswz);
            LDSM_X4(aH[0], aH[1], aH[2], aH[3], addr);
            LDSM_X4(aM[0], aM[1], aM[2], aM[3], addr + A_PART);
            LDSM_X4(aL[0], aL[1], aL[2], aL[3], addr + 2 * A_PART);
        }

#pragma unroll
        for (int bp = 0; bp < 3; bp++) {
            uint32_t Bt[8][4];
#pragma unroll
            for (int t = 0; t < 8; t++) {
                uint32_t addr = sB + bp * B_PART + boff0 + (uint32_t)(t * 2048) + (kcb ^ bswz);
                LDSM_X4(Bt[t][0], Bt[t][1], Bt[t][2], Bt[t][3], addr);
            }
            // products: bp=0(hi): A{hi,mid,lo}; bp=1(mid): A{hi,mid}; bp=2(lo): A{hi}
#pragma unroll
            for (int t = 0; t < 8; t++) {
                MMA_BF16(acc[2 * t],     aH, Bt[t][0], Bt[t][2]);
                MMA_BF16(acc[2 * t + 1], aH, Bt[t][1], Bt[t][3]);
            }
            if (bp < 2) {
#pragma unroll
                for (int t = 0; t < 8; t++) {
                    MMA_BF16(acc[2 * t],     aM, Bt[t][0], Bt[t][2]);
                    MMA_BF16(acc[2 * t + 1], aM, Bt[t][1], Bt[t][3]);
                }
            }
            if (bp == 0) {
#pragma unroll
                for (int t = 0; t < 8; t++) {
                    MMA_BF16(acc[2 * t],     aL, Bt[t][0], Bt[t][2]);
                    MMA_BF16(acc[2 * t + 1], aL, Bt[t][1], Bt[t][3]);
                }
            }
        }
    }

    // ---- epilogue ----
    // acc[j][e]: row = warpM*16 + (lane>>2) + (e>=2 ? 8 : 0)
    //            col = warpN*128 + j*8 + 2*(lane&3) + (e&1)
    const float gc = gamma[c];
    const bool useMax = (gc >= 0.f);

    unsigned long long best[2] = {0ull, 0ull};   // [0]: row g, [1]: row g+8
    float s = 0.f, s2 = 0.f;
#pragma unroll
    for (int j = 0; j < 16; j++) {
#pragma unroll
        for (int e = 0; e < 4; e++) {
            float v = acc[j][e];
            s += v;
            s2 = fmaf(v, v, s2);
            int k = warpN * 128 + j * 8 + 2 * (lane & 3) + (e & 1);
            unsigned key = fkey(v);
            if (!useMax) key = ~key;
            unsigned long long p = ((unsigned long long)key << 32) | (unsigned)(255 - k);
            int r = (e >> 1);
            best[r] = (p > best[r]) ? p : best[r];
        }
    }
    // combine across the 4 lanes sharing each row
#pragma unroll
    for (int sh = 1; sh <= 2; sh <<= 1) {
        unsigned long long o0 = __shfl_xor_sync(0xffffffffu, best[0], sh);
        unsigned long long o1 = __shfl_xor_sync(0xffffffffu, best[1], sh);
        best[0] = (o0 > best[0]) ? o0 : best[0];
        best[1] = (o1 > best[1]) ? o1 : best[1];
    }
    unsigned long long* red = (unsigned long long*)(smem + SM_RED);  // [2][128]
    if ((lane & 3) == 0) {
        int rl = warpM * 16 + (lane >> 2);
        red[warpN * 128 + rl] = best[0];
        red[warpN * 128 + rl + 8] = best[1];
    }

    // full-warp sum reduce
#pragma unroll
    for (int sh = 16; sh > 0; sh >>= 1) {
        s  += __shfl_xor_sync(0xffffffffu, s,  sh);
        s2 += __shfl_xor_sync(0xffffffffu, s2, sh);
    }
    float* wsum = (float*)(smem + SM_WSUM);
    if (lane == 0) { wsum[wid] = s; wsum[16 + wid] = s2; }
    __syncthreads();

    if (tid < BTILE) {
        unsigned long long p0 = red[tid];
        unsigned long long p1 = red[128 + tid];
        unsigned long long p = (p1 > p0) ? p1 : p0;
        unsigned key = (unsigned)(p >> 32);
        float v = fkey_inv(useMax ? key : ~key);
        int b = b0 + tid;
        g_val[(size_t)b * C_ + c] = v;
        g_idx[(size_t)b * C_ + c] = 255 - (int)(p & 0xFFu);
    }
    if (tid == 0) {
        float t1 = 0.f, t2 = 0.f;
#pragma unroll
        for (int w = 0; w < 16; w++) { t1 += wsum[w]; t2 += wsum[16 + w]; }
        atomicAdd(&g_sum[c], t1);
        atomicAdd(&g_sumsq[c], t2);
    }
}

// ---------------- finalize: BN affine + emit ----------------
__global__ void finalize_kernel(const float* __restrict__ gamma,
                                const float* __restrict__ beta,
                                float* __restrict__ out_codes,
                                float* __restrict__ out_mse) {
    int tid = blockIdx.x * 256 + threadIdx.x;
    if (tid >= B_ * C_) return;
    int c = tid & (C_ - 1);
    const float Ninv = 1.f / ((float)B_ * (float)K_);
    float mean = g_sum[c] * Ninv;
    float var  = fmaf(-mean, mean, g_sumsq[c] * Ninv);
    float scale = gamma[c] * rsqrtf(var + 1e-5f);
    float shift = fmaf(-mean, scale, beta[c]);
    out_codes[tid] = (float)g_idx[tid];
    out_mse[tid]   = fmaf(g_val[tid], scale, shift);
}

__global__ void copy_kernel(const float4* __restrict__ src,
                            float4* __restrict__ dst, int n4) {
    int i = blockIdx.x * blockDim.x + threadIdx.x;
    if (i < n4) dst[i] = src[i];
}

extern "C" void kernel_launch(void* const* d_in, const int* in_sizes, int n_in,
                              void* d_out, int out_size) {
    const float* inp   = (const float*)d_in[0];
    const float* cent  = (const float*)d_in[1];
    const float* gamma = (const float*)d_in[2];
    const float* beta  = (const float*)d_in[3];
    float* out = (float*)d_out;

    cudaFuncSetAttribute(score_kernel,
                         cudaFuncAttributeMaxDynamicSharedMemorySize, SM_TOTAL);

    init_kernel<<<1, 64>>>();

    dim3 grid(C_, B_ / BTILE);
    score_kernel<<<grid, 512, SM_TOTAL>>>(inp, cent, gamma);

    finalize_kernel<<<(B_ * C_ + 255) / 256, 256>>>(gamma, beta,
                                                    out, out + B_ * C_);

    if (out_size >= 2 * B_ * C_ + C_ * K_ * D_) {
        int n4 = (C_ * K_ * D_) / 4;
        copy_kernel<<<(n4 + 255) / 256, 256>>>((const float4*)cent,
                                               (float4*)(out + 2 * B_ * C_), n4);
    }
}

// round 5
// speedup vs baseline: 1.7946x; 1.2081x over previous
#include <cuda_runtime.h>
#include <cuda_bf16.h>
#include <cstdint>

#define B_ 8192
#define C_ 64
#define K_ 256
#define D_ 64
#define BTILE 128
#define NTILES 4096            // C_ * (B_/BTILE)
#define NBLK 148

// ---------------- scratch (static __device__) ----------------
__device__ float g_val[B_ * C_];
__device__ int   g_idx[B_ * C_];
__device__ float g_sum[C_];
__device__ float g_sumsq[C_];

__device__ __forceinline__ unsigned fkey(float f) {
    unsigned u = __float_as_uint(f);
    return (u & 0x80000000u) ? ~u : (u | 0x80000000u);
}
__device__ __forceinline__ float fkey_inv(unsigned key) {
    unsigned u = (key & 0x80000000u) ? (key ^ 0x80000000u) : ~key;
    return __uint_as_float(u);
}
__device__ __forceinline__ uint32_t smem_u32(const void* p) {
    uint32_t a;
    asm("{ .reg .u64 t; cvta.to.shared.u64 t, %1; cvt.u32.u64 %0, t; }" : "=r"(a) : "l"(p));
    return a;
}

#define LDSM_X4(r0, r1, r2, r3, addr) \
    asm volatile("ldmatrix.sync.aligned.m8n8.x4.shared.b16 {%0,%1,%2,%3}, [%4];" \
        : "=r"(r0), "=r"(r1), "=r"(r2), "=r"(r3) : "r"(addr))
#define MMA_BF16(c, a, b0, b1) \
    asm volatile("mma.sync.aligned.m16n8k16.row.col.f32.bf16.bf16.f32 " \
        "{%0,%1,%2,%3}, {%4,%5,%6,%7}, {%8,%9}, {%0,%1,%2,%3};" \
        : "+f"((c)[0]), "+f"((c)[1]), "+f"((c)[2]), "+f"((c)[3]) \
        : "r"((a)[0]), "r"((a)[1]), "r"((a)[2]), "r"((a)[3]), "r"(b0), "r"(b1))

__device__ __forceinline__ void split3(float x, uint16_t& h, uint16_t& m, uint16_t& l) {
    __nv_bfloat16 bh = __float2bfloat16_rn(x);
    float r1 = x - __bfloat162float(bh);
    __nv_bfloat16 bm = __float2bfloat16_rn(r1);
    float r2 = r1 - __bfloat162float(bm);
    __nv_bfloat16 bl = __float2bfloat16_rn(r2);
    h = __bfloat16_as_ushort(bh);
    m = __bfloat16_as_ushort(bm);
    l = __bfloat16_as_ushort(bl);
}

// ---------------- smem layout (bytes) ----------------
#define SM_RED   0                      // u64[2][128] = 2048
#define SM_WSUM  4096                   // f32[32]
#define SM_A     8192                   // 3 x 16384
#define SM_B     (8192 + 49152)         // 3 x 32768
#define SM_TOTAL (8192 + 49152 + 98304) // 155648
#define A_PART   16384
#define B_PART   32768

__global__ void init_kernel() {
    int t = threadIdx.x;
    if (t < C_) { g_sum[t] = 0.f; g_sumsq[t] = 0.f; }
}

__device__ __forceinline__ uint32_t sw_off(int row, int cbyte) {
    return (uint32_t)(row * 128 + (cbyte ^ ((row & 7) << 4)));
}

__global__ void __launch_bounds__(512, 1)
score_kernel(const float* __restrict__ inp, const float* __restrict__ cent,
             const float* __restrict__ gamma) {
    extern __shared__ char smem[];
    const int tid  = threadIdx.x;
    const int lane = tid & 31;
    const int wid  = tid >> 5;
    const int warpM = wid & 7;
    const int warpN = wid >> 3;

    const uint32_t smem_base = smem_u32(smem);
    const uint32_t sA = smem_base + SM_A;
    const uint32_t sB = smem_base + SM_B;

    // ldmatrix invariants (validated in R4)
    const int arow = warpM * 16 + (lane & 15);
    const uint32_t aoff0 = (uint32_t)(arow * 128);
    const uint32_t aswz = (uint32_t)((arow & 7) << 4);
    const int brow = warpN * 128 + (lane & 15);
    const uint32_t boff0 = (uint32_t)(brow * 128);
    const uint32_t bswz = (uint32_t)((brow & 7) << 4);
    const uint32_t lane16 = (uint32_t)(lane & 16);

    const int T0 = (blockIdx.x * NTILES) / NBLK;
    const int T1 = ((blockIdx.x + 1) * NTILES) / NBLK;

    int cur_c = -1;
    float gc = 0.f;
    bool useMax = true;

    for (int T = T0; T < T1; T++) {
        const int c  = T >> 6;
        const int b0 = (T & 63) * BTILE;

        // ---- (re)fill B on channel change ----
        if (c != cur_c) {
            __syncthreads();   // everyone done with old B
            cur_c = c;
            gc = gamma[c];
            useMax = (gc >= 0.f);
            const float* Bb = cent + (size_t)c * (K_ * D_);
            for (int t = tid; t < K_ * 16; t += 512) {
                int r = t >> 4;
                int d = (t & 15) << 2;
                float4 v = *(const float4*)(Bb + (size_t)r * D_ + d);
                uint16_t h[4], m[4], l[4];
                split3(v.x, h[0], m[0], l[0]);
                split3(v.y, h[1], m[1], l[1]);
                split3(v.z, h[2], m[2], l[2]);
                split3(v.w, h[3], m[3], l[3]);
                uint32_t o = sw_off(r, d * 2);
                *(uint64_t*)(smem + SM_B + o)              = (uint64_t)h[0] | ((uint64_t)h[1] << 16) | ((uint64_t)h[2] << 32) | ((uint64_t)h[3] << 48);
                *(uint64_t*)(smem + SM_B + B_PART + o)     = (uint64_t)m[0] | ((uint64_t)m[1] << 16) | ((uint64_t)m[2] << 32) | ((uint64_t)m[3] << 48);
                *(uint64_t*)(smem + SM_B + 2 * B_PART + o) = (uint64_t)l[0] | ((uint64_t)l[1] << 16) | ((uint64_t)l[2] << 32) | ((uint64_t)l[3] << 48);
            }
        }

        // ---- fill A tile ----
        {
            const float* Ab = inp + (size_t)b0 * (C_ * D_) + (size_t)c * D_;
            for (int t = tid; t < BTILE * 16; t += 512) {
                int r = t >> 4;
                int d = (t & 15) << 2;
                float4 v = *(const float4*)(Ab + (size_t)r * (C_ * D_) + d);
                uint16_t h[4], m[4], l[4];
                split3(v.x, h[0], m[0], l[0]);
                split3(v.y, h[1], m[1], l[1]);
                split3(v.z, h[2], m[2], l[2]);
                split3(v.w, h[3], m[3], l[3]);
                uint32_t o = sw_off(r, d * 2);
                *(uint64_t*)(smem + SM_A + o)              = (uint64_t)h[0] | ((uint64_t)h[1] << 16) | ((uint64_t)h[2] << 32) | ((uint64_t)h[3] << 48);
                *(uint64_t*)(smem + SM_A + A_PART + o)     = (uint64_t)m[0] | ((uint64_t)m[1] << 16) | ((uint64_t)m[2] << 32) | ((uint64_t)m[3] << 48);
                *(uint64_t*)(smem + SM_A + 2 * A_PART + o) = (uint64_t)l[0] | ((uint64_t)l[1] << 16) | ((uint64_t)l[2] << 32) | ((uint64_t)l[3] << 48);
            }
        }
        __syncthreads();

        // ---- MMA mainloop: one live B fragment at a time (reg pressure) ----
        float acc[16][4];
#pragma unroll
        for (int j = 0; j < 16; j++)
#pragma unroll
            for (int e = 0; e < 4; e++) acc[j][e] = 0.f;

#pragma unroll
        for (int ks = 0; ks < 4; ks++) {
            const uint32_t kcb = (uint32_t)(ks * 32) + lane16;
            uint32_t aH[4], aM[4], aL[4];
            {
                uint32_t addr = sA + aoff0 + (kcb ^ aswz);
                LDSM_X4(aH[0], aH[1], aH[2], aH[3], addr);
                LDSM_X4(aM[0], aM[1], aM[2], aM[3], addr + A_PART);
                LDSM_X4(aL[0], aL[1], aL[2], aL[3], addr + 2 * A_PART);
            }
            const uint32_t baddr = sB + boff0 + (kcb ^ bswz);
#pragma unroll
            for (int t = 0; t < 8; t++) {
                uint32_t b0r, b1r, b2r, b3r;
                uint32_t ta = baddr + (uint32_t)(t * 2048);
                // B-hi: pairs with aH, aM, aL
                LDSM_X4(b0r, b1r, b2r, b3r, ta);
                MMA_BF16(acc[2 * t],     aH, b0r, b2r);
                MMA_BF16(acc[2 * t + 1], aH, b1r, b3r);
                MMA_BF16(acc[2 * t],     aM, b0r, b2r);
                MMA_BF16(acc[2 * t + 1], aM, b1r, b3r);
                MMA_BF16(acc[2 * t],     aL, b0r, b2r);
                MMA_BF16(acc[2 * t + 1], aL, b1r, b3r);
                // B-mid: pairs with aH, aM
                LDSM_X4(b0r, b1r, b2r, b3r, ta + B_PART);
                MMA_BF16(acc[2 * t],     aH, b0r, b2r);
                MMA_BF16(acc[2 * t + 1], aH, b1r, b3r);
                MMA_BF16(acc[2 * t],     aM, b0r, b2r);
                MMA_BF16(acc[2 * t + 1], aM, b1r, b3r);
                // B-lo: pairs with aH
                LDSM_X4(b0r, b1r, b2r, b3r, ta + 2 * B_PART);
                MMA_BF16(acc[2 * t],     aH, b0r, b2r);
                MMA_BF16(acc[2 * t + 1], aH, b1r, b3r);
            }
        }

        // ---- epilogue ----
        unsigned long long best[2] = {0ull, 0ull};
        float s = 0.f, s2 = 0.f;
#pragma unroll
        for (int j = 0; j < 16; j++) {
#pragma unroll
            for (int e = 0; e < 4; e++) {
                float v = acc[j][e];
                s += v;
                s2 = fmaf(v, v, s2);
                int k = warpN * 128 + j * 8 + 2 * (lane & 3) + (e & 1);
                unsigned key = fkey(v);
                if (!useMax) key = ~key;
                unsigned long long p = ((unsigned long long)key << 32) | (unsigned)(255 - k);
                int r = (e >> 1);
                best[r] = (p > best[r]) ? p : best[r];
            }
        }
#pragma unroll
        for (int sh = 1; sh <= 2; sh <<= 1) {
            unsigned long long o0 = __shfl_xor_sync(0xffffffffu, best[0], sh);
            unsigned long long o1 = __shfl_xor_sync(0xffffffffu, best[1], sh);
            best[0] = (o0 > best[0]) ? o0 : best[0];
            best[1] = (o1 > best[1]) ? o1 : best[1];
        }
        unsigned long long* red = (unsigned long long*)(smem + SM_RED);
        if ((lane & 3) == 0) {
            int rl = warpM * 16 + (lane >> 2);
            red[warpN * 128 + rl] = best[0];
            red[warpN * 128 + rl + 8] = best[1];
        }
#pragma unroll
        for (int sh = 16; sh > 0; sh >>= 1) {
            s  += __shfl_xor_sync(0xffffffffu, s,  sh);
            s2 += __shfl_xor_sync(0xffffffffu, s2, sh);
        }
        float* wsum = (float*)(smem + SM_WSUM);
        if (lane == 0) { wsum[wid] = s; wsum[16 + wid] = s2; }
        __syncthreads();

        if (tid < BTILE) {
            unsigned long long p0 = red[tid];
            unsigned long long p1 = red[128 + tid];
            unsigned long long p = (p1 > p0) ? p1 : p0;
            unsigned key = (unsigned)(p >> 32);
            float v = fkey_inv(useMax ? key : ~key);
            int b = b0 + tid;
            g_val[(size_t)b * C_ + c] = v;
            g_idx[(size_t)b * C_ + c] = 255 - (int)(p & 0xFFu);
        }
        if (tid == 0) {
            float t1 = 0.f, t2 = 0.f;
#pragma unroll
            for (int w = 0; w < 16; w++) { t1 += wsum[w]; t2 += wsum[16 + w]; }
            atomicAdd(&g_sum[c], t1);
            atomicAdd(&g_sumsq[c], t2);
        }
        __syncthreads();   // red/wsum consumed; safe to refill next tile
    }
}

// ---------------- finalize: BN affine + emit ----------------
__global__ void finalize_kernel(const float* __restrict__ gamma,
                                const float* __restrict__ beta,
                                float* __restrict__ out_codes,
                                float* __restrict__ out_mse) {
    int tid = blockIdx.x * 256 + threadIdx.x;
    if (tid >= B_ * C_) return;
    int c = tid & (C_ - 1);
    const float Ninv = 1.f / ((float)B_ * (float)K_);
    float mean = g_sum[c] * Ninv;
    float var  = fmaf(-mean, mean, g_sumsq[c] * Ninv);
    float scale = gamma[c] * rsqrtf(var + 1e-5f);
    float shift = fmaf(-mean, scale, beta[c]);
    out_codes[tid] = (float)g_idx[tid];
    out_mse[tid]   = fmaf(g_val[tid], scale, shift);
}

__global__ void copy_kernel(const float4* __restrict__ src,
                            float4* __restrict__ dst, int n4) {
    int i = blockIdx.x * blockDim.x + threadIdx.x;
    if (i < n4) dst[i] = src[i];
}

extern "C" void kernel_launch(void* const* d_in, const int* in_sizes, int n_in,
                              void* d_out, int out_size) {
    const float* inp   = (const float*)d_in[0];
    const float* cent  = (const float*)d_in[1];
    const float* gamma = (const float*)d_in[2];
    const float* beta  = (const float*)d_in[3];
    float* out = (float*)d_out;

    cudaFuncSetAttribute(score_kernel,
                         cudaFuncAttributeMaxDynamicSharedMemorySize, SM_TOTAL);

    init_kernel<<<1, 64>>>();

    score_kernel<<<NBLK, 512, SM_TOTAL>>>(inp, cent, gamma);

    finalize_kernel<<<(B_ * C_ + 255) / 256, 256>>>(gamma, beta,
                                                    out, out + B_ * C_);

    if (out_size >= 2 * B_ * C_ + C_ * K_ * D_) {
        int n4 = (C_ * K_ * D_) / 4;
        copy_kernel<<<(n4 + 255) / 256, 256>>>((const float4*)cent,
                                               (float4*)(out + 2 * B_ * C_), n4);
    }
}